// round 5
// baseline (speedup 1.0000x reference)
#include <cuda_runtime.h>
#include <math.h>

#define DS   128
#define DSM  (DS - 1)
#define D3   (DS * DS * DS)

// Tile: 32 x 8 x 4 real cells = 1024; 512 threads.
#define TXD   32
#define TYD   8
#define TZD   4
#define CELLS (TXD * TYD * TZD)  // 1024
#define NTHR  512

#define HX   36
#define HY   12
#define HZ   8
#define HXY  (HX * HY)           // 432
#define HTOT (HXY * HZ)          // 3456

struct SM {
    float2         xy[HTOT];     // (x,y) interleaved
    float2         vxy[HTOT];    // (vx,vy) interleaved
    float          z[HTOT];
    float          vz[HTOT];
    unsigned short list[CELLS];  // halo-space indices of occupied cells
    int            cnt;
};

__device__ __forceinline__ float fast_rsqrt(float x) {
    float r; asm("rsqrt.approx.f32 %0, %1;" : "=f"(r) : "f"(x)); return r;
}

// Stencil contribution at halo offset o.  coef = KN*(dist-2)/dist + ETA*vn/dist
//   = KN - 2KN*rcd + ETA*vnu*rcd^2   with rcd = rsqrt(sq), vnu = dv.d
#define CONTRIB(o)                                                            \
    {                                                                         \
        float2 nxy = S->xy[(o)];                                              \
        float  nz  = S->z[(o)];                                               \
        float dx = X - nxy.x, dy = Y - nxy.y, dz = Z - nz;                    \
        float sq = dx * dx + dy * dy + dz * dz;                               \
        if (sq < 4.0f) {                                                      \
            float2 nv  = S->vxy[(o)];                                         \
            float  nvz = S->vz[(o)];                                          \
            float rcd = fast_rsqrt(sq);                                       \
            float vnu = (VX - nv.x) * dx + (VY - nv.y) * dy + (VZ - nvz) * dz;\
            float coef = fmaf(ETA * vnu, rcd * rcd,                           \
                              fmaf(-1000000.0f, rcd, 500000.0f));             \
            fx = fmaf(coef, dx, fx);                                          \
            fy = fmaf(coef, dy, fy);                                          \
            fz = fmaf(coef, dz, fz);                                          \
        }                                                                     \
    }

// Half of the 80-shift pruned stencil: shifts with parity(ox+oy+oz) == PAR.
template <int PAR>
__device__ __forceinline__ void half_stencil(
    const SM* __restrict__ S, int cc,
    float X, float Y, float Z, float VX, float VY, float VZ,
    float ETA, float& fx, float& fy, float& fz)
{
    #pragma unroll
    for (int oz = -2; oz <= 2; ++oz)
    #pragma unroll
    for (int oy = -2; oy <= 2; ++oy)
    #pragma unroll
    for (int ox = -2; ox <= 2; ++ox) {
        const int s2 = oz * oz + oy * oy + ox * ox;
        if (s2 == 0 || s2 > 6) continue;
        if (((ox + oy + oz) & 1) != PAR) continue;
        CONTRIB(cc + oz * HXY + oy * HX + ox);
    }
}

__global__ __launch_bounds__(NTHR, 2) void dem_step(
    const float* __restrict__ xg,  const float* __restrict__ yg,
    const float* __restrict__ zg,  const float* __restrict__ vxg,
    const float* __restrict__ vyg, const float* __restrict__ vzg,
    const float* __restrict__ mg,  float* __restrict__ out, float ETA)
{
    extern __shared__ char smraw[];
    SM* S = (SM*)smraw;

    const int x0 = blockIdx.x * TXD;
    const int y0 = blockIdx.y * TYD;
    const int z0 = blockIdx.z * TZD;
    const int tid = threadIdx.x;

    if (tid == 0) S->cnt = 0;

    // Cooperative halo fill (periodic wrap: & 127)
    for (int i = tid; i < HTOT; i += NTHR) {
        int lx = i % HX;
        int t  = i / HX;
        int ly = t % HY;
        int lz = t / HY;
        int gx = (x0 + lx - 2) & DSM;
        int gy = (y0 + ly - 2) & DSM;
        int gz = (z0 + lz - 2) & DSM;
        int g  = (gz << 14) | (gy << 7) | gx;
        S->xy[i]  = make_float2(__ldg(xg + g),  __ldg(yg + g));
        S->vxy[i] = make_float2(__ldg(vxg + g), __ldg(vyg + g));
        S->z[i]   = __ldg(zg + g);
        S->vz[i]  = __ldg(vzg + g);
    }
    __syncthreads();

    // Warp-aggregated compaction: each thread inspects 2 cells of the tile.
    #pragma unroll
    for (int half = 0; half < CELLS / NTHR; ++half) {
        const int i  = tid + half * NTHR;        // tile-linear cell id
        const int lx = i & 31;
        const int ly = (i >> 5) & 7;
        const int lz = i >> 8;
        const float m = __ldg(mg + (((z0 + lz) << 14) | ((y0 + ly) << 7) | (x0 + lx)));
        const int c   = (lz + 2) * HXY + (ly + 2) * HX + (lx + 2);
        unsigned bal = __ballot_sync(0xFFFFFFFFu, m != 0.0f);
        int base = 0;
        if ((tid & 31) == 0 && bal) base = atomicAdd(&S->cnt, __popc(bal));
        base = __shfl_sync(0xFFFFFFFFu, base, 0);
        if (m != 0.0f) {
            int rank = __popc(bal & ((1u << (tid & 31)) - 1u));
            S->list[base + rank] = (unsigned short)c;
        }
    }
    __syncthreads();

    const int cnt2 = 2 * S->cnt;     // two threads per particle
    const int sub  = tid & 1;
    const float KN = 500000.0f;

    for (int t2 = tid; t2 < cnt2; t2 += NTHR) {
        const int cc = S->list[t2 >> 1];
        const float2 XYp  = S->xy[cc];     // pair lanes hit same addr: broadcast
        const float2 VXYp = S->vxy[cc];
        const float X = XYp.x,  Y = XYp.y,  Z  = S->z[cc];
        const float VX = VXYp.x, VY = VXYp.y, VZ = S->vz[cc];

        float fx = 0.0f, fy = 0.0f, fz = 0.0f;

        // Split the 80 pruned shifts between the pair by coordinate parity.
        if (sub == 0) half_stencil<0>(S, cc, X, Y, Z, VX, VY, VZ, ETA, fx, fy, fz);
        else          half_stencil<1>(S, cc, X, Y, Z, VX, VY, VZ, ETA, fx, fy, fz);

        // Excluded shifts (s^2 >= 8) only matter via "contact with empty
        // cell" (rolled value 0), requiring |own pos| < 2 — origin corner
        // only. Rare: even lane of the pair handles all of them.
        if (sub == 0 && X * X + Y * Y + Z * Z < 4.0f) {
            #pragma unroll 1
            for (int oz = -2; oz <= 2; ++oz)
            #pragma unroll 1
            for (int oy = -2; oy <= 2; ++oy)
            #pragma unroll 1
            for (int ox = -2; ox <= 2; ++ox) {
                int s2 = oz * oz + oy * oy + ox * ox;
                if (s2 <= 6) continue;
                CONTRIB(cc + oz * HXY + oy * HX + ox);
            }
        }

        // Pair reduction: lanes 2p / 2p+1 are in the same warp and exit the
        // loop together (cnt2 even), so the pair is always converged here.
        unsigned mk = __activemask();
        fx += __shfl_xor_sync(mk, fx, 1);
        fy += __shfl_xor_sync(mk, fy, 1);
        fz += __shfl_xor_sync(mk, fz, 1);
        if (sub != 0) continue;

        // Boundary overlap forces (mask == 1 for list entries)
        float bl = (X != 0.0f && X < 1.0f) ? 1.0f : 0.0f;
        float br = (X > 126.0f) ? 1.0f : 0.0f;
        float bb = (Y != 0.0f && Y < 1.0f) ? 1.0f : 0.0f;
        float bt = (Y > 126.0f) ? 1.0f : 0.0f;
        float bf = (Z != 0.0f && Z < 1.0f) ? 1.0f : 0.0f;
        float bk = (Z > 126.0f) ? 1.0f : 0.0f;
        float fxb = KN * bl * (1.0f - X) - KN * br * (X - 126.0f) - ETA * VX * (bl + br);
        float fyb = KN * bb * (1.0f - Y) - KN * bt * (Y - 126.0f) - ETA * VY * (bb + bt);
        float fzb = KN * bf * (1.0f - Z) - KN * bk * (Z - 126.0f) - ETA * VZ * (bf + bk);

        float vxn = VX + 1e-4f * (-fx + fxb);
        float vyn = VY + 1e-4f * (-9.8f - fy + fyb);
        float vzn = VZ + 1e-4f * (-fz + fzb);
        float xn = X + 1e-4f * vxn;
        float yn = Y + 1e-4f * vyn;
        float zn = Z + 1e-4f * vzn;

        // Cell-list relocation (round half-even like jnp.round; comp==0
        // invalid; out-of-range dropped).
        int cx = __float2int_rn(xn);
        int cy = __float2int_rn(yn);
        int cz = __float2int_rn(zn);
        if (cx >= 1 && cx <= 127 && cy >= 1 && cy <= 127 && cz >= 1 && cz <= 127) {
            int l = (cz << 14) | (cy << 7) | cx;
            out[l]          = xn;
            out[D3 + l]     = yn;
            out[2 * D3 + l] = zn;
            out[3 * D3 + l] = vxn;
            out[4 * D3 + l] = vyn;
            out[5 * D3 + l] = vzn;
            out[6 * D3 + l] = 1.0f;
        }
    }
}

extern "C" void kernel_launch(void* const* d_in, const int* in_sizes, int n_in,
                              void* d_out, int out_size)
{
    const float* xg  = (const float*)d_in[0];
    const float* yg  = (const float*)d_in[1];
    const float* zg  = (const float*)d_in[2];
    const float* vxg = (const float*)d_in[3];
    const float* vyg = (const float*)d_in[4];
    const float* vzg = (const float*)d_in[5];
    const float* mg  = (const float*)d_in[6];
    float* out = (float*)d_out;

    // Reference's "zero at lo" collapses to: zero everything, scatter at ln.
    cudaMemsetAsync(d_out, 0, (size_t)out_size * sizeof(float), 0);

    double alpha = -log(0.7) / M_PI;
    double gamma = alpha / sqrt(alpha * alpha + 1.0);
    float  eta   = (float)(2.0 * gamma * sqrt(500000.0 * 1.0));

    const size_t smem = sizeof(SM);   // ~85 KB
    cudaFuncSetAttribute(dem_step, cudaFuncAttributeMaxDynamicSharedMemorySize, (int)smem);

    dim3 block(NTHR, 1, 1);
    dim3 grid(DS / TXD, DS / TYD, DS / TZD);   // 4 x 16 x 32 = 2048 blocks
    dem_step<<<grid, block, smem>>>(xg, yg, zg, vxg, vyg, vzg, mg, out, eta);
}